// round 14
// baseline (speedup 1.0000x reference)
#include <cuda_runtime.h>
#include <cuda_fp16.h>
#include <cstdint>

#define SEQ   1024
#define HID   1024
#define BATCH 4
#define NROWS (BATCH * 1024)
#define NKC   512
#define MF    (BATCH * 512)        // 2048 folded rows
#define MFE   (MF + 64)            // extended with row-512 tile (4 used, 60 zero)

// ---------------- static device scratch ----------------
__device__ __half g_cosh[NKC * NKC];     // cos quadrant [n<512][k<512], fp16
__device__ __half g_sinh[NKC * NKC];
__device__ __half g_XeE[MFE * NKC];      // double-even fold of X (fp16); rows 2048+b = row-512 fold
__device__ __half g_XoO[MFE * NKC];      // double-odd fold; ext rows stay zero
__device__ float  g_x512e[MFE];          // fold of X[.,512]; ext rows: X[b,512,512]
__device__ __half g_PeT[NKC * MFE];      // Pe^T: [k][b*512+i]; cols 2048+b = P[b,512,k]
__device__ __half g_QoT[NKC * MFE];
__device__ float  g_p512[NROWS];         // alternating row-sum of X (fp32)

// ---------------- helpers ----------------
__device__ __forceinline__ uint32_t smem_u32(const void* p) {
    return (uint32_t)__cvta_generic_to_shared(p);
}
__device__ __forceinline__ void cpa(uint32_t s, const void* g) {
    asm volatile("cp.async.cg.shared.global [%0], [%1], 16;" :: "r"(s), "l"(g));
}
#define CP_COMMIT asm volatile("cp.async.commit_group;" ::: "memory")
#define CP_WAIT1  asm volatile("cp.async.wait_group 1;" ::: "memory")

__device__ __forceinline__ void mma16(float* d, const uint32_t* a, const uint32_t* b) {
    asm volatile(
        "mma.sync.aligned.m16n8k16.row.col.f32.f16.f16.f32 "
        "{%0,%1,%2,%3}, {%4,%5,%6,%7}, {%8,%9}, {%0,%1,%2,%3};"
        : "+f"(d[0]), "+f"(d[1]), "+f"(d[2]), "+f"(d[3])
        : "r"(a[0]), "r"(a[1]), "r"(a[2]), "r"(a[3]), "r"(b[0]), "r"(b[1]));
}
__device__ __forceinline__ void ldm4(uint32_t* r, uint32_t saddr) {
    asm volatile("ldmatrix.sync.aligned.m8n8.x4.shared.b16 {%0,%1,%2,%3}, [%4];"
        : "=r"(r[0]), "=r"(r[1]), "=r"(r[2]), "=r"(r[3]) : "r"(saddr));
}

// ---------------- fused: double fold of X + Nyquist row-sums + table fill ----------------
__global__ __launch_bounds__(256)
void foldX2(const float* __restrict__ X) {
    if (blockIdx.x >= 512) {
        int fb = (blockIdx.x - 512) + 256 * blockIdx.y;   // 0..1023
        int idx = fb * 256 + threadIdx.x;                 // 512*512 table entries
        int j = idx >> 9, k = idx & 511;
        int m = (j * k) & 1023;
        float s, c;
        sincospif((float)m * (1.0f / 512.0f), &s, &c);
        g_cosh[idx] = __float2half_rn(c);
        g_sinh[idx] = __float2half_rn(s);
        return;
    }

    __shared__ float se[512], so[512];
    __shared__ float s_red[8];
    __shared__ float sx5[2];
    const int tid = threadIdx.x;
    const int rloc = tid >> 7;
    const int l128 = tid & 127;
    const int kg = l128 * 4;
    const int i = blockIdx.x;
    const int b = blockIdx.y;
    const int r = rloc ? (i == 0 ? b * 1024 + 512 : b * 1024 + 1024 - i)
                       : (b * 1024 + i);
    const float* Xrow = X + (size_t)r * HID;

    float4 fx = *(const float4*)(Xrow + kg);
    float fv[4] = { fx.x, fx.y, fx.z, fx.w };
    float e[4], o[4];
    float part = 0.f;
    #pragma unroll
    for (int j = 0; j < 4; j++) {
        int k = kg + j;
        if (k == 0) {
            e[0] = fv[0]; o[0] = 0.f;
            part += fv[0];
        } else {
            float m = Xrow[1024 - k];
            float sum = fv[j] + m, dif = fv[j] - m;
            e[j] = sum;
            o[j] = dif;
            part += (k & 1) ? -sum : sum;
        }
    }
    if (kg == 0) {
        float x5 = Xrow[512];
        sx5[rloc] = x5;
        part += x5;
    }
    if (rloc == 1 && i != 0) {
        *(float4*)(se + kg) = make_float4(e[0], e[1], e[2], e[3]);
        *(float4*)(so + kg) = make_float4(o[0], o[1], o[2], o[3]);
    }
    #pragma unroll
    for (int off = 16; off; off >>= 1) part += __shfl_xor_sync(0xFFFFFFFFu, part, off);
    if ((tid & 31) == 0) s_red[tid >> 5] = part;
    __syncthreads();
    if ((tid & 127) == 0) {
        int w0 = rloc * 4;
        g_p512[r] = s_red[w0] + s_red[w0 + 1] + s_red[w0 + 2] + s_red[w0 + 3];
    }
    if (rloc == 0) {
        float eE[4], oO[4];
        if (i == 0) {
            #pragma unroll
            for (int j = 0; j < 4; j++) { eE[j] = e[j]; oO[j] = 0.f; }
        } else {
            #pragma unroll
            for (int j = 0; j < 4; j++) {
                eE[j] = e[j] + se[kg + j];
                oO[j] = o[j] - so[kg + j];
            }
        }
        size_t dst = ((size_t)b * 512 + i) * NKC + kg;
        *(half2*)(g_XeE + dst)     = __floats2half2_rn(eE[0], eE[1]);
        *(half2*)(g_XeE + dst + 2) = __floats2half2_rn(eE[2], eE[3]);
        *(half2*)(g_XoO + dst)     = __floats2half2_rn(oO[0], oO[1]);
        *(half2*)(g_XoO + dst + 2) = __floats2half2_rn(oO[2], oO[3]);
        if (kg == 0)
            g_x512e[b * 512 + i] = (i == 0) ? sx5[0] : sx5[0] + sx5[1];
    } else if (i == 0) {
        size_t dst = ((size_t)MF + b) * NKC + kg;
        *(half2*)(g_XeE + dst)     = __floats2half2_rn(e[0], e[1]);
        *(half2*)(g_XeE + dst + 2) = __floats2half2_rn(e[2], e[3]);
        if (kg == 0) g_x512e[MF + b] = sx5[1];   // X[b,512,512]
    }
}

// ---------------- stage 1: PeT/QoT = (XeE@C)^T, (XoO@S)^T over 2112 rows ----------------
// CTA 64(M) x 64(N), 8 warps (2M x 4N), warp tile 32x16, BK=32, 16 chunks.
// 2 CTAs/SM, ldmatrix, 3-stage cp.async pipeline.
#define S1_BUF  5120
#define O1_XE4  0
#define O1_XO4  (1280 * 4)
#define O1_CB4  (2560 * 4)
#define O1_SB4  (3840 * 4)
#define SMEM1_BYTES (3 * S1_BUF * 4)
#define TSTR1   72

__global__ __launch_bounds__(256, 2)
void stage1() {
    extern __shared__ uint32_t dsu[];

    const int tid = threadIdx.x;
    const int lane = tid & 31, wid = tid >> 5;
    const int gr = lane >> 2, tg = lane & 3;
    const int m_base = (wid & 1) * 32, n_base = (wid >> 1) * 16;
    const int m0 = blockIdx.y * 64;
    const int n0 = blockIdx.x * 64;

    const uint32_t aoff = (uint32_t)((m_base + (lane & 7) + ((lane >> 3) & 1) * 8) * 80
                                     + ((lane >> 4) & 1) * 16);
    const uint32_t boff = (uint32_t)(((lane & 7) + ((lane >> 4) & 1) * 8) * 80
                                     + ((lane >> 3) & 1) * 16);

    float dP[2][2][4] = {};
    float dQ[2][2][4] = {};

    auto load = [&](int ch, int buf) {
        const int k0h = ch * 32;
        uint32_t* base = dsu + buf * S1_BUF;
        int r = tid >> 2, c = tid & 3;
        uint32_t off = r * 20 + c * 4;
        size_t ga = (size_t)(m0 + r) * NKC + k0h + c * 8;
        size_t gb = (size_t)(n0 + r) * NKC + k0h + c * 8;
        cpa(smem_u32(base + off),        g_XeE + ga);
        cpa(smem_u32(base + 1280 + off), g_XoO + ga);
        cpa(smem_u32(base + 2560 + off), g_cosh + gb);
        cpa(smem_u32(base + 3840 + off), g_sinh + gb);
    };

    auto compute = [&](int buf) {
        const uint32_t base = smem_u32(dsu + buf * S1_BUF);
        #pragma unroll
        for (int j = 0; j < 2; j++) {
            uint32_t aE[2][4], aO[2][4];
            #pragma unroll
            for (int mi = 0; mi < 2; mi++) {
                ldm4(aE[mi], base + O1_XE4 + aoff + mi * 1280 + j * 32);
                ldm4(aO[mi], base + O1_XO4 + aoff + mi * 1280 + j * 32);
            }
            uint32_t bc[4], bs[4];
            uint32_t nb = (uint32_t)(n_base * 80) + j * 32 + boff;
            ldm4(bc, base + O1_CB4 + nb);
            ldm4(bs, base + O1_SB4 + nb);
            #pragma unroll
            for (int mi = 0; mi < 2; mi++)
                #pragma unroll
                for (int ni = 0; ni < 2; ni++) {
                    mma16(dP[mi][ni], aE[mi], &bc[ni * 2]);
                    mma16(dQ[mi][ni], aO[mi], &bs[ni * 2]);
                }
        }
    };

    load(0, 0); CP_COMMIT;
    load(1, 1); CP_COMMIT;
    #pragma unroll 1
    for (int ch = 0; ch < 16; ch++) {
        CP_WAIT1;
        __syncthreads();
        compute(ch % 3);
        if (ch + 2 < 16) { load(ch + 2, (ch + 2) % 3); CP_COMMIT; }
    }
    __syncthreads();

    // epilogue: Pe += (-1)^k x512e; transpose 64x64 tile; write PeT/QoT
    __half* trs = (__half*)dsu;
    #pragma unroll
    for (int mi = 0; mi < 2; mi++) {
        int rl = m_base + mi * 16 + gr;
        float xa = g_x512e[m0 + rl];
        float xb = g_x512e[m0 + rl + 8];
        #pragma unroll
        for (int ni = 0; ni < 2; ni++) {
            int cl = n_base + ni * 8 + 2 * tg;
            trs[cl * TSTR1 + rl]           = __float2half_rn(dP[mi][ni][0] + xa);
            trs[(cl + 1) * TSTR1 + rl]     = __float2half_rn(dP[mi][ni][1] - xa);
            trs[cl * TSTR1 + rl + 8]       = __float2half_rn(dP[mi][ni][2] + xb);
            trs[(cl + 1) * TSTR1 + rl + 8] = __float2half_rn(dP[mi][ni][3] - xb);
        }
    }
    __syncthreads();
    #pragma unroll
    for (int pass = 0; pass < 2; pass++) {
        int idx = tid + pass * 256;
        int c = idx >> 3, s = idx & 7;
        uint4 v = *(uint4*)((uint32_t*)trs + c * (TSTR1 / 2) + s * 4);
        *(uint4*)(g_PeT + (size_t)(n0 + c) * MFE + m0 + s * 8) = v;
    }
    __syncthreads();
    #pragma unroll
    for (int mi = 0; mi < 2; mi++) {
        int rl = m_base + mi * 16 + gr;
        #pragma unroll
        for (int ni = 0; ni < 2; ni++) {
            int cl = n_base + ni * 8 + 2 * tg;
            trs[cl * TSTR1 + rl]           = __float2half_rn(dQ[mi][ni][0]);
            trs[(cl + 1) * TSTR1 + rl]     = __float2half_rn(dQ[mi][ni][1]);
            trs[cl * TSTR1 + rl + 8]       = __float2half_rn(dQ[mi][ni][2]);
            trs[(cl + 1) * TSTR1 + rl + 8] = __float2half_rn(dQ[mi][ni][3]);
        }
    }
    __syncthreads();
    #pragma unroll
    for (int pass = 0; pass < 2; pass++) {
        int idx = tid + pass * 256;
        int c = idx >> 3, s = idx & 7;
        uint4 v = *(uint4*)((uint32_t*)trs + c * (TSTR1 / 2) + s * 4);
        *(uint4*)(g_QoT + (size_t)(n0 + c) * MFE + m0 + s * 8) = v;
    }
}

// ---------------- tail: row 512 GEMV + Nyquist column (MUFU) ----------------
__global__ __launch_bounds__(256)
void tail512(float* __restrict__ out) {
    const int b = blockIdx.y;
    const int wid = threadIdx.x >> 5, lane = threadIdx.x & 31;
    if (blockIdx.x < 64) {
        const int k = blockIdx.x * 8 + wid;
        const __half* row = g_PeT + (size_t)k * MFE + b * 512;
        float acc = 0.f;
        #pragma unroll 4
        for (int q = 0; q < 16; q++) acc += __half2float(row[lane + q * 32]);
        float sgn = (lane & 1) ? -1.f : 1.f;
        acc *= sgn;
        #pragma unroll
        for (int o = 16; o; o >>= 1) acc += __shfl_xor_sync(0xFFFFFFFFu, acc, o);
        if (lane == 0) {
            float v = acc + __half2float(g_PeT[(size_t)k * MFE + MF + b]);
            float* orow = out + ((size_t)b * SEQ + 512) * HID;
            orow[k] = v;
            if (k != 0) orow[HID - k] = v;
        }
    } else {
        __shared__ float pv[1024];
        for (int q = threadIdx.x; q < 1024; q += 256)
            pv[q] = g_p512[b * 1024 + q];
        __syncthreads();
        const int n = (blockIdx.x - 64) * 8 + wid;
        if (n <= 512) {
            float acc = 0.f;
            #pragma unroll 8
            for (int q = 0; q < 32; q++) {
                int i = q * 32 + lane;
                int m = (n * i) & 1023;
                acc += cospif((float)m * (1.0f / 512.0f)) * pv[i];
            }
            #pragma unroll
            for (int o = 16; o; o >>= 1) acc += __shfl_xor_sync(0xFFFFFFFFu, acc, o);
            if (lane == 0) {
                out[((size_t)b * SEQ + n) * HID + 512] = acc;
                if (n >= 1 && n <= 511)
                    out[((size_t)b * SEQ + 1024 - n) * HID + 512] = acc;
            }
        }
    }
}

// ---------------- stage 2: A = C@Pe + corr, B = S@Qo; 4-quadrant scatter ----------------
// CTA 64(n) x 64(k), 8 warps (2M x 4N), warp 32x16, BK=32, 16 chunks, 2 CTAs/SM.
#define S2_BUF  5120
#define O2_CB4  0
#define O2_SB4  (1280 * 4)
#define O2_PB4  (2560 * 4)
#define O2_QB4  (3840 * 4)
#define SMEM2_BYTES (3 * S2_BUF * 4)

__global__ __launch_bounds__(256, 2)
void stage2(float* __restrict__ out) {
    extern __shared__ uint32_t dsu[];

    const int tid = threadIdx.x;
    const int lane = tid & 31, wid = tid >> 5;
    const int gr = lane >> 2, tg = lane & 3;
    const int m_base = (wid & 1) * 32, n_base = (wid >> 1) * 16;
    const int k0   = blockIdx.x * 64;
    const int row0 = blockIdx.y * 64;
    const int b    = blockIdx.z;

    const uint32_t aoff = (uint32_t)((m_base + (lane & 7) + ((lane >> 3) & 1) * 8) * 80
                                     + ((lane >> 4) & 1) * 16);
    const uint32_t boff = (uint32_t)(((lane & 7) + ((lane >> 4) & 1) * 8) * 80
                                     + ((lane >> 3) & 1) * 16);

    float dA[2][2][4] = {};
    float dB[2][2][4] = {};

    auto load = [&](int ch, int buf) {
        const int i0 = ch * 32;
        uint32_t* base = dsu + buf * S2_BUF;
        int r = tid >> 2, c = tid & 3;
        uint32_t off = r * 20 + c * 4;
        size_t ga = (size_t)(row0 + r) * NKC + i0 + c * 8;
        size_t gb = (size_t)(k0 + r) * MFE + b * 512 + i0 + c * 8;
        cpa(smem_u32(base + off),        g_cosh + ga);
        cpa(smem_u32(base + 1280 + off), g_sinh + ga);
        cpa(smem_u32(base + 2560 + off), g_PeT + gb);
        cpa(smem_u32(base + 3840 + off), g_QoT + gb);
    };

    auto compute = [&](int buf) {
        const uint32_t base = smem_u32(dsu + buf * S2_BUF);
        #pragma unroll
        for (int j = 0; j < 2; j++) {
            uint32_t aC[2][4], aS[2][4];
            #pragma unroll
            for (int mi = 0; mi < 2; mi++) {
                ldm4(aC[mi], base + O2_CB4 + aoff + mi * 1280 + j * 32);
                ldm4(aS[mi], base + O2_SB4 + aoff + mi * 1280 + j * 32);
            }
            uint32_t bP[4], bQ[4];
            uint32_t nb = (uint32_t)(n_base * 80) + j * 32 + boff;
            ldm4(bP, base + O2_PB4 + nb);
            ldm4(bQ, base + O2_QB4 + nb);
            #pragma unroll
            for (int mi = 0; mi < 2; mi++)
                #pragma unroll
                for (int ni = 0; ni < 2; ni++) {
                    mma16(dA[mi][ni], aC[mi], &bP[ni * 2]);
                    mma16(dB[mi][ni], aS[mi], &bQ[ni * 2]);
                }
        }
    };

    load(0, 0); CP_COMMIT;
    load(1, 1); CP_COMMIT;
    #pragma unroll 1
    for (int ch = 0; ch < 16; ch++) {
        CP_WAIT1;
        __syncthreads();
        compute(ch % 3);
        if (ch + 2 < 16) { load(ch + 2, (ch + 2) % 3); CP_COMMIT; }
    }

    __syncthreads();
    float* sc = (float*)dsu;
    if (tid < 64)
        sc[tid] = __half2float(g_PeT[(size_t)(k0 + tid) * MFE + MF + b]);
    __syncthreads();

    const float sgn = (gr & 1) ? -1.f : 1.f;
    float* outb = out + (size_t)b * SEQ * HID;
    #pragma unroll
    for (int mi = 0; mi < 2; mi++) {
        #pragma unroll
        for (int ni = 0; ni < 2; ni++) {
            int lc = n_base + ni * 8 + 2 * tg;
            int col = k0 + lc;
            float c0corr = sgn * sc[lc];
            float c1corr = sgn * sc[lc + 1];
            #pragma unroll
            for (int h = 0; h < 2; h++) {
                int n = row0 + m_base + mi * 16 + gr + h * 8;
                float A0 = dA[mi][ni][h * 2]     + c0corr;
                float A1 = dA[mi][ni][h * 2 + 1] + c1corr;
                float B0 = dB[mi][ni][h * 2];
                float B1 = dB[mi][ni][h * 2 + 1];
                float d0 = A0 - B0, d1 = A1 - B1;
                float s0 = A0 + B0, s1 = A1 + B1;
                float* orow = outb + (size_t)n * HID;
                *(float2*)&orow[col] = make_float2(d0, d1);
                if (col != 0) orow[HID - col] = s0;
                orow[HID - col - 1] = s1;
                if (n != 0) {
                    float* mrow = outb + (size_t)(HID - n) * HID;
                    *(float2*)&mrow[col] = make_float2(s0, s1);
                    if (col != 0) mrow[HID - col] = d0;
                    mrow[HID - col - 1] = d1;
                }
            }
        }
    }
}

// ---------------- launcher ----------------
extern "C" void kernel_launch(void* const* d_in, const int* in_sizes, int n_in,
                              void* d_out, int out_size) {
    const float* X = (const float*)d_in[0];
    float* out = (float*)d_out;

    cudaFuncSetAttribute(stage1, cudaFuncAttributeMaxDynamicSharedMemorySize, SMEM1_BYTES);
    cudaFuncSetAttribute(stage2, cudaFuncAttributeMaxDynamicSharedMemorySize, SMEM2_BYTES);

    foldX2<<<dim3(512 + 256, 4), 256>>>(X);
    stage1<<<dim3(8, 33), 256, SMEM1_BYTES>>>();
    tail512<<<dim3(129, 4), 256>>>(out);
    stage2<<<dim3(8, 8, 4), 256, SMEM2_BYTES>>>(out);
}

// round 15
// speedup vs baseline: 1.1069x; 1.1069x over previous
#include <cuda_runtime.h>
#include <cuda_fp16.h>
#include <cstdint>

#define SEQ   1024
#define HID   1024
#define BATCH 4
#define NROWS (BATCH * 1024)
#define NKC   512
#define MF    (BATCH * 512)        // 2048 folded rows
#define MFE   (MF + 64)            // extended with row-512 tile (4 used, 60 zero)

// ---------------- static device scratch ----------------
__device__ __half g_cosh[NKC * NKC];     // cos quadrant [n<512][k<512], fp16
__device__ __half g_sinh[NKC * NKC];
__device__ __half g_XeE[MFE * NKC];      // double-even fold of X (fp16); rows 2048+b = row-512 fold
__device__ __half g_XoO[MFE * NKC];      // double-odd fold; ext rows stay zero
__device__ float  g_x512e[MFE];          // fold of X[.,512]; ext rows: X[b,512,512]
__device__ __half g_PeT[NKC * MFE];      // Pe^T: [k][b*512+i]; cols 2048+b = P[b,512,k]
__device__ __half g_QoT[NKC * MFE];
__device__ float  g_p512[NROWS];         // alternating row-sum of X (fp32)

// ---------------- helpers ----------------
__device__ __forceinline__ uint32_t smem_u32(const void* p) {
    return (uint32_t)__cvta_generic_to_shared(p);
}
__device__ __forceinline__ void cpa(uint32_t s, const void* g) {
    asm volatile("cp.async.cg.shared.global [%0], [%1], 16;" :: "r"(s), "l"(g));
}
#define CP_COMMIT asm volatile("cp.async.commit_group;" ::: "memory")
#define CP_WAIT1  asm volatile("cp.async.wait_group 1;" ::: "memory")

__device__ __forceinline__ void mma16(float* d, const uint32_t* a, const uint32_t* b) {
    asm volatile(
        "mma.sync.aligned.m16n8k16.row.col.f32.f16.f16.f32 "
        "{%0,%1,%2,%3}, {%4,%5,%6,%7}, {%8,%9}, {%0,%1,%2,%3};"
        : "+f"(d[0]), "+f"(d[1]), "+f"(d[2]), "+f"(d[3])
        : "r"(a[0]), "r"(a[1]), "r"(a[2]), "r"(a[3]), "r"(b[0]), "r"(b[1]));
}
__device__ __forceinline__ void ldm4(uint32_t* r, uint32_t saddr) {
    asm volatile("ldmatrix.sync.aligned.m8n8.x4.shared.b16 {%0,%1,%2,%3}, [%4];"
        : "=r"(r[0]), "=r"(r[1]), "=r"(r[2]), "=r"(r[3]) : "r"(saddr));
}

// ---------------- fused: double fold of X + Nyquist row-sums + table fill ----------------
__global__ __launch_bounds__(256)
void foldX2(const float* __restrict__ X) {
    if (blockIdx.x >= 512) {
        int fb = (blockIdx.x - 512) + 256 * blockIdx.y;   // 0..1023
        int idx = fb * 256 + threadIdx.x;                 // 512*512 table entries
        int j = idx >> 9, k = idx & 511;
        int m = (j * k) & 1023;
        float s, c;
        sincospif((float)m * (1.0f / 512.0f), &s, &c);
        g_cosh[idx] = __float2half_rn(c);
        g_sinh[idx] = __float2half_rn(s);
        return;
    }

    __shared__ float se[512], so[512];
    __shared__ float s_red[8];
    __shared__ float sx5[2];
    const int tid = threadIdx.x;
    const int rloc = tid >> 7;
    const int l128 = tid & 127;
    const int kg = l128 * 4;
    const int i = blockIdx.x;
    const int b = blockIdx.y;
    const int r = rloc ? (i == 0 ? b * 1024 + 512 : b * 1024 + 1024 - i)
                       : (b * 1024 + i);
    const float* Xrow = X + (size_t)r * HID;

    float4 fx = *(const float4*)(Xrow + kg);
    float fv[4] = { fx.x, fx.y, fx.z, fx.w };
    float e[4], o[4];
    float part = 0.f;
    #pragma unroll
    for (int j = 0; j < 4; j++) {
        int k = kg + j;
        if (k == 0) {
            e[0] = fv[0]; o[0] = 0.f;
            part += fv[0];
        } else {
            float m = Xrow[1024 - k];
            float sum = fv[j] + m, dif = fv[j] - m;
            e[j] = sum;
            o[j] = dif;
            part += (k & 1) ? -sum : sum;
        }
    }
    if (kg == 0) {
        float x5 = Xrow[512];
        sx5[rloc] = x5;
        part += x5;
    }
    if (rloc == 1 && i != 0) {
        *(float4*)(se + kg) = make_float4(e[0], e[1], e[2], e[3]);
        *(float4*)(so + kg) = make_float4(o[0], o[1], o[2], o[3]);
    }
    #pragma unroll
    for (int off = 16; off; off >>= 1) part += __shfl_xor_sync(0xFFFFFFFFu, part, off);
    if ((tid & 31) == 0) s_red[tid >> 5] = part;
    __syncthreads();
    if ((tid & 127) == 0) {
        int w0 = rloc * 4;
        g_p512[r] = s_red[w0] + s_red[w0 + 1] + s_red[w0 + 2] + s_red[w0 + 3];
    }
    if (rloc == 0) {
        float eE[4], oO[4];
        if (i == 0) {
            #pragma unroll
            for (int j = 0; j < 4; j++) { eE[j] = e[j]; oO[j] = 0.f; }
        } else {
            #pragma unroll
            for (int j = 0; j < 4; j++) {
                eE[j] = e[j] + se[kg + j];
                oO[j] = o[j] - so[kg + j];
            }
        }
        size_t dst = ((size_t)b * 512 + i) * NKC + kg;
        *(half2*)(g_XeE + dst)     = __floats2half2_rn(eE[0], eE[1]);
        *(half2*)(g_XeE + dst + 2) = __floats2half2_rn(eE[2], eE[3]);
        *(half2*)(g_XoO + dst)     = __floats2half2_rn(oO[0], oO[1]);
        *(half2*)(g_XoO + dst + 2) = __floats2half2_rn(oO[2], oO[3]);
        if (kg == 0)
            g_x512e[b * 512 + i] = (i == 0) ? sx5[0] : sx5[0] + sx5[1];
    } else if (i == 0) {
        size_t dst = ((size_t)MF + b) * NKC + kg;
        *(half2*)(g_XeE + dst)     = __floats2half2_rn(e[0], e[1]);
        *(half2*)(g_XeE + dst + 2) = __floats2half2_rn(e[2], e[3]);
        if (kg == 0) g_x512e[MF + b] = sx5[1];   // X[b,512,512]
    }
}

// ---------------- stage 1: PeT/QoT = (XeE@C)^T, (XoO@S)^T over 2112 rows ----------------
// CTA 64(M) x 128(N), 8 warps (2M x 4N), warp 32x32, BK=32, 16 chunks (round-12 proven).
#define S1_BUF  7680
#define O1_XE4  0
#define O1_XO4  (1280 * 4)
#define O1_CB4  (2560 * 4)
#define O1_SB4  (5120 * 4)
#define SMEM1_BYTES (3 * S1_BUF * 4)
#define TSTR1   72

__global__ __launch_bounds__(256)
void stage1() {
    extern __shared__ uint32_t dsu[];

    const int tid = threadIdx.x;
    const int lane = tid & 31, wid = tid >> 5;
    const int gr = lane >> 2, tg = lane & 3;
    const int m_base = (wid & 1) * 32, n_base = (wid >> 1) * 32;
    const int m0 = blockIdx.y * 64;
    const int n0 = blockIdx.x * 128;

    const uint32_t aoff = (uint32_t)((m_base + (lane & 7) + ((lane >> 3) & 1) * 8) * 80
                                     + ((lane >> 4) & 1) * 16);
    const uint32_t boff = (uint32_t)(((lane & 7) + ((lane >> 4) & 1) * 8) * 80
                                     + ((lane >> 3) & 1) * 16);

    float dP[2][4][4] = {};
    float dQ[2][4][4] = {};

    auto load = [&](int ch, int buf) {
        const int k0h = ch * 32;
        uint32_t* base = dsu + buf * S1_BUF;
        {
            int r = tid >> 2, c = tid & 3;
            uint32_t off = r * 20 + c * 4;
            size_t ga = (size_t)(m0 + r) * NKC + k0h + c * 8;
            cpa(smem_u32(base + off),        g_XeE + ga);
            cpa(smem_u32(base + 1280 + off), g_XoO + ga);
        }
        #pragma unroll
        for (int i = 0; i < 2; i++) {
            int t = tid + i * 256;
            int r = t >> 2, c = t & 3;
            uint32_t off = r * 20 + c * 4;
            size_t gb = (size_t)(n0 + r) * NKC + k0h + c * 8;
            cpa(smem_u32(base + 2560 + off), g_cosh + gb);
            cpa(smem_u32(base + 5120 + off), g_sinh + gb);
        }
    };

    auto compute = [&](int buf) {
        const uint32_t base = smem_u32(dsu + buf * S1_BUF);
        #pragma unroll
        for (int j = 0; j < 2; j++) {
            uint32_t aE[4], aO[4], aE2[4], aO2[4];
            ldm4(aE,  base + O1_XE4 + aoff + j * 32);
            ldm4(aO,  base + O1_XO4 + aoff + j * 32);
            ldm4(aE2, base + O1_XE4 + aoff + 1280 + j * 32);
            ldm4(aO2, base + O1_XO4 + aoff + 1280 + j * 32);
            uint32_t bc[2][4], bs[2][4];
            #pragma unroll
            for (int g = 0; g < 2; g++) {
                uint32_t nb = (uint32_t)((n_base + g * 16) * 80) + j * 32 + boff;
                ldm4(bc[g], base + O1_CB4 + nb);
                ldm4(bs[g], base + O1_SB4 + nb);
            }
            #pragma unroll
            for (int ni = 0; ni < 4; ni++) {
                mma16(dP[0][ni], aE,  &bc[ni >> 1][(ni & 1) * 2]);
                mma16(dQ[0][ni], aO,  &bs[ni >> 1][(ni & 1) * 2]);
                mma16(dP[1][ni], aE2, &bc[ni >> 1][(ni & 1) * 2]);
                mma16(dQ[1][ni], aO2, &bs[ni >> 1][(ni & 1) * 2]);
            }
        }
    };

    load(0, 0); CP_COMMIT;
    load(1, 1); CP_COMMIT;
    #pragma unroll 1
    for (int ch = 0; ch < 16; ch++) {
        CP_WAIT1;
        __syncthreads();
        compute(ch % 3);
        if (ch + 2 < 16) { load(ch + 2, (ch + 2) % 3); CP_COMMIT; }
    }
    __syncthreads();

    // epilogue: Pe += (-1)^k x512e; transpose 64x128 tiles; write PeT/QoT
    __half* trs = (__half*)dsu;
    #pragma unroll
    for (int mi = 0; mi < 2; mi++) {
        int rl = m_base + mi * 16 + gr;
        float xa = g_x512e[m0 + rl];
        float xb = g_x512e[m0 + rl + 8];
        #pragma unroll
        for (int ni = 0; ni < 4; ni++) {
            int cl = n_base + ni * 8 + 2 * tg;
            trs[cl * TSTR1 + rl]           = __float2half_rn(dP[mi][ni][0] + xa);
            trs[(cl + 1) * TSTR1 + rl]     = __float2half_rn(dP[mi][ni][1] - xa);
            trs[cl * TSTR1 + rl + 8]       = __float2half_rn(dP[mi][ni][2] + xb);
            trs[(cl + 1) * TSTR1 + rl + 8] = __float2half_rn(dP[mi][ni][3] - xb);
        }
    }
    __syncthreads();
    #pragma unroll
    for (int pass = 0; pass < 4; pass++) {
        int idx = tid + pass * 256;
        int c = idx >> 3, s = idx & 7;
        uint4 v = *(uint4*)((uint32_t*)trs + c * (TSTR1 / 2) + s * 4);
        *(uint4*)(g_PeT + (size_t)(n0 + c) * MFE + m0 + s * 8) = v;
    }
    __syncthreads();
    #pragma unroll
    for (int mi = 0; mi < 2; mi++) {
        int rl = m_base + mi * 16 + gr;
        #pragma unroll
        for (int ni = 0; ni < 4; ni++) {
            int cl = n_base + ni * 8 + 2 * tg;
            trs[cl * TSTR1 + rl]           = __float2half_rn(dQ[mi][ni][0]);
            trs[(cl + 1) * TSTR1 + rl]     = __float2half_rn(dQ[mi][ni][1]);
            trs[cl * TSTR1 + rl + 8]       = __float2half_rn(dQ[mi][ni][2]);
            trs[(cl + 1) * TSTR1 + rl + 8] = __float2half_rn(dQ[mi][ni][3]);
        }
    }
    __syncthreads();
    #pragma unroll
    for (int pass = 0; pass < 4; pass++) {
        int idx = tid + pass * 256;
        int c = idx >> 3, s = idx & 7;
        uint4 v = *(uint4*)((uint32_t*)trs + c * (TSTR1 / 2) + s * 4);
        *(uint4*)(g_QoT + (size_t)(n0 + c) * MFE + m0 + s * 8) = v;
    }
}

// ---------------- tail: row 512 GEMV + Nyquist column (MUFU) ----------------
__global__ __launch_bounds__(256)
void tail512(float* __restrict__ out) {
    const int b = blockIdx.y;
    const int wid = threadIdx.x >> 5, lane = threadIdx.x & 31;
    if (blockIdx.x < 64) {
        const int k = blockIdx.x * 8 + wid;
        const __half* row = g_PeT + (size_t)k * MFE + b * 512;
        float acc = 0.f;
        #pragma unroll 4
        for (int q = 0; q < 16; q++) acc += __half2float(row[lane + q * 32]);
        float sgn = (lane & 1) ? -1.f : 1.f;
        acc *= sgn;
        #pragma unroll
        for (int o = 16; o; o >>= 1) acc += __shfl_xor_sync(0xFFFFFFFFu, acc, o);
        if (lane == 0) {
            float v = acc + __half2float(g_PeT[(size_t)k * MFE + MF + b]);
            float* orow = out + ((size_t)b * SEQ + 512) * HID;
            orow[k] = v;
            if (k != 0) orow[HID - k] = v;
        }
    } else {
        __shared__ float pv[1024];
        for (int q = threadIdx.x; q < 1024; q += 256)
            pv[q] = g_p512[b * 1024 + q];
        __syncthreads();
        const int n = (blockIdx.x - 64) * 8 + wid;
        if (n <= 512) {
            float acc = 0.f;
            #pragma unroll 8
            for (int q = 0; q < 32; q++) {
                int i = q * 32 + lane;
                int m = (n * i) & 1023;
                acc += cospif((float)m * (1.0f / 512.0f)) * pv[i];
            }
            #pragma unroll
            for (int o = 16; o; o >>= 1) acc += __shfl_xor_sync(0xFFFFFFFFu, acc, o);
            if (lane == 0) {
                out[((size_t)b * SEQ + n) * HID + 512] = acc;
                if (n >= 1 && n <= 511)
                    out[((size_t)b * SEQ + 1024 - n) * HID + 512] = acc;
            }
        }
    }
}

// ---------------- stage 2: A = C@Pe + corr, B = S@Qo; STAGED coalesced scatter ----------------
// Round-12 mainloop: CTA 128(n) x 64(k), 8 warps 4Mx2N, warp 32x32, BK=32, 16 chunks.
#define S2_BUF  7680
#define O2_CB4  0
#define O2_SB4  (2560 * 4)
#define O2_PB4  (5120 * 4)
#define O2_QB4  (6400 * 4)
#define SMEM2_BYTES (3 * S2_BUF * 4)
#define OST 68   // staging tile stride (floats)

__global__ __launch_bounds__(256)
void stage2(float* __restrict__ out) {
    extern __shared__ uint32_t dsu[];

    const int tid = threadIdx.x;
    const int lane = tid & 31, wid = tid >> 5;
    const int gr = lane >> 2, tg = lane & 3;
    const int m_base = (wid & 3) * 32, n_base = (wid >> 2) * 32;
    const int k0   = blockIdx.x * 64;
    const int row0 = blockIdx.y * 128;
    const int b    = blockIdx.z;

    const uint32_t aoff = (uint32_t)((m_base + (lane & 7) + ((lane >> 3) & 1) * 8) * 80
                                     + ((lane >> 4) & 1) * 16);
    const uint32_t boff = (uint32_t)(((lane & 7) + ((lane >> 4) & 1) * 8) * 80
                                     + ((lane >> 3) & 1) * 16);

    float dA[2][4][4] = {};
    float dB[2][4][4] = {};

    auto load = [&](int ch, int buf) {
        const int i0 = ch * 32;
        uint32_t* base = dsu + buf * S2_BUF;
        #pragma unroll
        for (int i = 0; i < 2; i++) {
            int t2 = tid + i * 256;
            int r = t2 >> 2, c = t2 & 3;
            uint32_t off = r * 20 + c * 4;
            size_t gsrc = (size_t)(row0 + r) * NKC + i0 + c * 8;
            cpa(smem_u32(base + off),        g_cosh + gsrc);
            cpa(smem_u32(base + 2560 + off), g_sinh + gsrc);
        }
        {
            int r = tid >> 2, c = tid & 3;
            uint32_t off = r * 20 + c * 4;
            size_t gsrc = (size_t)(k0 + r) * MFE + b * 512 + i0 + c * 8;
            cpa(smem_u32(base + 5120 + off), g_PeT + gsrc);
            cpa(smem_u32(base + 6400 + off), g_QoT + gsrc);
        }
    };

    auto compute = [&](int buf) {
        const uint32_t base = smem_u32(dsu + buf * S2_BUF);
        #pragma unroll
        for (int j = 0; j < 2; j++) {
            uint32_t aC[2][4], aS[2][4];
            #pragma unroll
            for (int mi = 0; mi < 2; mi++) {
                ldm4(aC[mi], base + O2_CB4 + aoff + mi * 1280 + j * 32);
                ldm4(aS[mi], base + O2_SB4 + aoff + mi * 1280 + j * 32);
            }
            uint32_t bP[2][4], bQ[2][4];
            #pragma unroll
            for (int g = 0; g < 2; g++) {
                uint32_t nb = (uint32_t)((n_base + g * 16) * 80) + j * 32 + boff;
                ldm4(bP[g], base + O2_PB4 + nb);
                ldm4(bQ[g], base + O2_QB4 + nb);
            }
            #pragma unroll
            for (int mi = 0; mi < 2; mi++)
                #pragma unroll
                for (int ni = 0; ni < 4; ni++) {
                    mma16(dA[mi][ni], aC[mi], &bP[ni >> 1][(ni & 1) * 2]);
                    mma16(dB[mi][ni], aS[mi], &bQ[ni >> 1][(ni & 1) * 2]);
                }
        }
    };

    load(0, 0); CP_COMMIT;
    load(1, 1); CP_COMMIT;
    #pragma unroll 1
    for (int ch = 0; ch < 16; ch++) {
        CP_WAIT1;
        __syncthreads();
        compute(ch % 3);
        if (ch + 2 < 16) { load(ch + 2, (ch + 2) % 3); CP_COMMIT; }
    }

    // ---- corr values into registers ----
    __syncthreads();
    float* scp = (float*)dsu;
    if (tid < 64)
        scp[tid] = __half2float(g_PeT[(size_t)(k0 + tid) * MFE + MF + b]);
    __syncthreads();
    const float sgn = (gr & 1) ? -1.f : 1.f;
    float corr[4][2];
    #pragma unroll
    for (int ni = 0; ni < 4; ni++) {
        int lc = n_base + ni * 8 + 2 * tg;
        corr[ni][0] = sgn * scp[lc];
        corr[ni][1] = sgn * scp[lc + 1];
    }
    __syncthreads();

    float* st = (float*)dsu;           // staging tile [128][OST]
    float* outb = out + (size_t)b * SEQ * HID;

    // ======== pass 1: d = A - B → direct quadrant + double-mirror quadrant ========
    #pragma unroll
    for (int mi = 0; mi < 2; mi++) {
        #pragma unroll
        for (int ni = 0; ni < 4; ni++) {
            int c = n_base + ni * 8 + 2 * tg;
            #pragma unroll
            for (int h = 0; h < 2; h++) {
                int r = m_base + mi * 16 + gr + h * 8;
                st[r * OST + c]     = (dA[mi][ni][h * 2]     + corr[ni][0]) - dB[mi][ni][h * 2];
                st[r * OST + c + 1] = (dA[mi][ni][h * 2 + 1] + corr[ni][1]) - dB[mi][ni][h * 2 + 1];
            }
        }
    }
    __syncthreads();
    // direct: out[row0+r][k0 + c], coalesced float4
    for (int t = tid; t < 2048; t += 256) {
        int r = t >> 4, c4 = (t & 15) * 4;
        float4 v = *(float4*)&st[r * OST + c4];
        *(float4*)&outb[(size_t)(row0 + r) * HID + k0 + c4] = v;
    }
    // double mirror: out[1024-n][1024-k'], n = row0+r (skip n==0), reversed cols
    for (int t = tid; t < 2048; t += 256) {
        int r = t >> 4, seg = t & 15;
        int n = row0 + r;
        if (n == 0) continue;
        float* mrow = outb + (size_t)(1024 - n) * HID;
        if (seg < 15) {
            int oc = 964 - k0 + seg * 4;
            float4 v;
            v.x = st[r * OST + (60 - seg * 4)];
            v.y = st[r * OST + (60 - seg * 4 - 1)];
            v.z = st[r * OST + (60 - seg * 4 - 2)];
            v.w = st[r * OST + (60 - seg * 4 - 3)];
            *(float4*)&mrow[oc] = v;
        } else {
            mrow[961 - k0] = st[r * OST + 63];
            mrow[962 - k0] = st[r * OST + 62];
            mrow[963 - k0] = st[r * OST + 61];
            if (k0 > 0) mrow[1024 - k0] = st[r * OST + 0];
        }
    }
    __syncthreads();

    // ======== pass 2: s = A + B → row-mirror quadrant + col-mirror quadrant ========
    #pragma unroll
    for (int mi = 0; mi < 2; mi++) {
        #pragma unroll
        for (int ni = 0; ni < 4; ni++) {
            int c = n_base + ni * 8 + 2 * tg;
            #pragma unroll
            for (int h = 0; h < 2; h++) {
                int r = m_base + mi * 16 + gr + h * 8;
                st[r * OST + c]     = (dA[mi][ni][h * 2]     + corr[ni][0]) + dB[mi][ni][h * 2];
                st[r * OST + c + 1] = (dA[mi][ni][h * 2 + 1] + corr[ni][1]) + dB[mi][ni][h * 2 + 1];
            }
        }
    }
    __syncthreads();
    // row mirror: out[1024-n][k0 + c], direct cols, skip n==0
    for (int t = tid; t < 2048; t += 256) {
        int r = t >> 4, c4 = (t & 15) * 4;
        int n = row0 + r;
        if (n == 0) continue;
        float4 v = *(float4*)&st[r * OST + c4];
        *(float4*)&outb[(size_t)(1024 - n) * HID + k0 + c4] = v;
    }
    // col mirror: out[n][1024-k'], reversed cols
    for (int t = tid; t < 2048; t += 256) {
        int r = t >> 4, seg = t & 15;
        int n = row0 + r;
        float* orow = outb + (size_t)n * HID;
        if (seg < 15) {
            int oc = 964 - k0 + seg * 4;
            float4 v;
            v.x = st[r * OST + (60 - seg * 4)];
            v.y = st[r * OST + (60 - seg * 4 - 1)];
            v.z = st[r * OST + (60 - seg * 4 - 2)];
            v.w = st[r * OST + (60 - seg * 4 - 3)];
            *(float4*)&orow[oc] = v;
        } else {
            orow[961 - k0] = st[r * OST + 63];
            orow[962 - k0] = st[r * OST + 62];
            orow[963 - k0] = st[r * OST + 61];
            if (k0 > 0) orow[1024 - k0] = st[r * OST + 0];
        }
    }
}

// ---------------- launcher ----------------
extern "C" void kernel_launch(void* const* d_in, const int* in_sizes, int n_in,
                              void* d_out, int out_size) {
    const float* X = (const float*)d_in[0];
    float* out = (float*)d_out;

    cudaFuncSetAttribute(stage1, cudaFuncAttributeMaxDynamicSharedMemorySize, SMEM1_BYTES);
    cudaFuncSetAttribute(stage2, cudaFuncAttributeMaxDynamicSharedMemorySize, SMEM2_BYTES);

    foldX2<<<dim3(512 + 256, 4), 256>>>(X);
    stage1<<<dim3(4, 33), 256, SMEM1_BYTES>>>();
    tail512<<<dim3(129, 4), 256>>>(out);
    stage2<<<dim3(8, 4, 4), 256, SMEM2_BYTES>>>(out);
}

// round 16
// speedup vs baseline: 1.1189x; 1.0109x over previous
#include <cuda_runtime.h>
#include <cuda_fp16.h>
#include <cstdint>

#define SEQ   1024
#define HID   1024
#define BATCH 4
#define NROWS (BATCH * 1024)
#define NKC   512
#define MF    (BATCH * 512)        // 2048 folded rows
#define MFE   (MF + 64)            // extended with row-512 tile (4 used, 60 zero)

// ---------------- static device scratch ----------------
__device__ __half g_cosh[NKC * NKC];     // cos quadrant [n<512][k<512], fp16
__device__ __half g_sinh[NKC * NKC];
__device__ __half g_XeE[MFE * NKC];      // double-even fold of X (fp16); rows 2048+b = row-512 fold
__device__ __half g_XoO[MFE * NKC];      // double-odd fold; ext rows stay zero
__device__ float  g_x512e[MFE];          // fold of X[.,512]; ext rows: X[b,512,512]
__device__ __half g_PeT[NKC * MFE];      // Pe^T: [k][b*512+i]; cols 2048+b = P[b,512,k]
__device__ __half g_QoT[NKC * MFE];
__device__ float  g_p512[NROWS];         // alternating row-sum of X (fp32)

// ---------------- helpers ----------------
__device__ __forceinline__ uint32_t smem_u32(const void* p) {
    return (uint32_t)__cvta_generic_to_shared(p);
}
__device__ __forceinline__ void cpa(uint32_t s, const void* g) {
    asm volatile("cp.async.cg.shared.global [%0], [%1], 16;" :: "r"(s), "l"(g));
}
#define CP_COMMIT asm volatile("cp.async.commit_group;" ::: "memory")
#define CP_WAIT2  asm volatile("cp.async.wait_group 2;" ::: "memory")
#define CP_WAIT1  asm volatile("cp.async.wait_group 1;" ::: "memory")
#define CP_WAIT0  asm volatile("cp.async.wait_group 0;" ::: "memory")

__device__ __forceinline__ void mma16(float* d, const uint32_t* a, const uint32_t* b) {
    asm volatile(
        "mma.sync.aligned.m16n8k16.row.col.f32.f16.f16.f32 "
        "{%0,%1,%2,%3}, {%4,%5,%6,%7}, {%8,%9}, {%0,%1,%2,%3};"
        : "+f"(d[0]), "+f"(d[1]), "+f"(d[2]), "+f"(d[3])
        : "r"(a[0]), "r"(a[1]), "r"(a[2]), "r"(a[3]), "r"(b[0]), "r"(b[1]));
}
__device__ __forceinline__ void ldm4(uint32_t* r, uint32_t saddr) {
    asm volatile("ldmatrix.sync.aligned.m8n8.x4.shared.b16 {%0,%1,%2,%3}, [%4];"
        : "=r"(r[0]), "=r"(r[1]), "=r"(r[2]), "=r"(r[3]) : "r"(saddr));
}

// pipeline tail-aware wait: at iter ch of 16, groups committed are 0..min(ch+2,15)
#define PIPE_WAIT(ch) do { \
    if ((ch) <= 13) { CP_WAIT2; } \
    else if ((ch) == 14) { CP_WAIT1; } \
    else { CP_WAIT0; } \
} while (0)

// ---------------- fused: double fold of X + Nyquist row-sums + table fill ----------------
__global__ __launch_bounds__(256)
void foldX2(const float* __restrict__ X) {
    if (blockIdx.x >= 512) {
        int fb = (blockIdx.x - 512) + 256 * blockIdx.y;   // 0..1023
        int idx = fb * 256 + threadIdx.x;                 // 512*512 table entries
        int j = idx >> 9, k = idx & 511;
        int m = (j * k) & 1023;
        float s, c;
        sincospif((float)m * (1.0f / 512.0f), &s, &c);
        g_cosh[idx] = __float2half_rn(c);
        g_sinh[idx] = __float2half_rn(s);
        return;
    }

    __shared__ float se[512], so[512];
    __shared__ float s_red[8];
    __shared__ float sx5[2];
    const int tid = threadIdx.x;
    const int rloc = tid >> 7;
    const int l128 = tid & 127;
    const int kg = l128 * 4;
    const int i = blockIdx.x;
    const int b = blockIdx.y;
    const int r = rloc ? (i == 0 ? b * 1024 + 512 : b * 1024 + 1024 - i)
                       : (b * 1024 + i);
    const float* Xrow = X + (size_t)r * HID;

    float4 fx = *(const float4*)(Xrow + kg);
    float fv[4] = { fx.x, fx.y, fx.z, fx.w };
    float e[4], o[4];
    float part = 0.f;
    #pragma unroll
    for (int j = 0; j < 4; j++) {
        int k = kg + j;
        if (k == 0) {
            e[0] = fv[0]; o[0] = 0.f;
            part += fv[0];
        } else {
            float m = Xrow[1024 - k];
            float sum = fv[j] + m, dif = fv[j] - m;
            e[j] = sum;
            o[j] = dif;
            part += (k & 1) ? -sum : sum;
        }
    }
    if (kg == 0) {
        float x5 = Xrow[512];
        sx5[rloc] = x5;
        part += x5;
    }
    if (rloc == 1 && i != 0) {
        *(float4*)(se + kg) = make_float4(e[0], e[1], e[2], e[3]);
        *(float4*)(so + kg) = make_float4(o[0], o[1], o[2], o[3]);
    }
    #pragma unroll
    for (int off = 16; off; off >>= 1) part += __shfl_xor_sync(0xFFFFFFFFu, part, off);
    if ((tid & 31) == 0) s_red[tid >> 5] = part;
    __syncthreads();
    if ((tid & 127) == 0) {
        int w0 = rloc * 4;
        g_p512[r] = s_red[w0] + s_red[w0 + 1] + s_red[w0 + 2] + s_red[w0 + 3];
    }
    if (rloc == 0) {
        float eE[4], oO[4];
        if (i == 0) {
            #pragma unroll
            for (int j = 0; j < 4; j++) { eE[j] = e[j]; oO[j] = 0.f; }
        } else {
            #pragma unroll
            for (int j = 0; j < 4; j++) {
                eE[j] = e[j] + se[kg + j];
                oO[j] = o[j] - so[kg + j];
            }
        }
        size_t dst = ((size_t)b * 512 + i) * NKC + kg;
        *(half2*)(g_XeE + dst)     = __floats2half2_rn(eE[0], eE[1]);
        *(half2*)(g_XeE + dst + 2) = __floats2half2_rn(eE[2], eE[3]);
        *(half2*)(g_XoO + dst)     = __floats2half2_rn(oO[0], oO[1]);
        *(half2*)(g_XoO + dst + 2) = __floats2half2_rn(oO[2], oO[3]);
        if (kg == 0)
            g_x512e[b * 512 + i] = (i == 0) ? sx5[0] : sx5[0] + sx5[1];
    } else if (i == 0) {
        size_t dst = ((size_t)MF + b) * NKC + kg;
        *(half2*)(g_XeE + dst)     = __floats2half2_rn(e[0], e[1]);
        *(half2*)(g_XeE + dst + 2) = __floats2half2_rn(e[2], e[3]);
        if (kg == 0) g_x512e[MF + b] = sx5[1];   // X[b,512,512]
    }
}

// ---------------- stage 1: PeT/QoT = (XeE@C)^T, (XoO@S)^T over 2112 rows ----------------
// CTA 64(M) x 128(N), 8 warps (2M x 4N), warp 32x32, BK=32, 16 chunks.
// 4-stage cp.async pipeline (prefetch distance ~2.5 chunks).
#define S1_BUF  7680
#define O1_XE4  0
#define O1_XO4  (1280 * 4)
#define O1_CB4  (2560 * 4)
#define O1_SB4  (5120 * 4)
#define SMEM1_BYTES (4 * S1_BUF * 4)
#define TSTR1   72

__global__ __launch_bounds__(256)
void stage1() {
    extern __shared__ uint32_t dsu[];

    const int tid = threadIdx.x;
    const int lane = tid & 31, wid = tid >> 5;
    const int gr = lane >> 2, tg = lane & 3;
    const int m_base = (wid & 1) * 32, n_base = (wid >> 1) * 32;
    const int m0 = blockIdx.y * 64;
    const int n0 = blockIdx.x * 128;

    const uint32_t aoff = (uint32_t)((m_base + (lane & 7) + ((lane >> 3) & 1) * 8) * 80
                                     + ((lane >> 4) & 1) * 16);
    const uint32_t boff = (uint32_t)(((lane & 7) + ((lane >> 4) & 1) * 8) * 80
                                     + ((lane >> 3) & 1) * 16);

    float dP[2][4][4] = {};
    float dQ[2][4][4] = {};

    auto load = [&](int ch, int buf) {
        const int k0h = ch * 32;
        uint32_t* base = dsu + buf * S1_BUF;
        {
            int r = tid >> 2, c = tid & 3;
            uint32_t off = r * 20 + c * 4;
            size_t ga = (size_t)(m0 + r) * NKC + k0h + c * 8;
            cpa(smem_u32(base + off),        g_XeE + ga);
            cpa(smem_u32(base + 1280 + off), g_XoO + ga);
        }
        #pragma unroll
        for (int i = 0; i < 2; i++) {
            int t = tid + i * 256;
            int r = t >> 2, c = t & 3;
            uint32_t off = r * 20 + c * 4;
            size_t gb = (size_t)(n0 + r) * NKC + k0h + c * 8;
            cpa(smem_u32(base + 2560 + off), g_cosh + gb);
            cpa(smem_u32(base + 5120 + off), g_sinh + gb);
        }
    };

    auto compute = [&](int buf) {
        const uint32_t base = smem_u32(dsu + buf * S1_BUF);
        #pragma unroll
        for (int j = 0; j < 2; j++) {
            uint32_t aE[4], aO[4], aE2[4], aO2[4];
            ldm4(aE,  base + O1_XE4 + aoff + j * 32);
            ldm4(aO,  base + O1_XO4 + aoff + j * 32);
            ldm4(aE2, base + O1_XE4 + aoff + 1280 + j * 32);
            ldm4(aO2, base + O1_XO4 + aoff + 1280 + j * 32);
            uint32_t bc[2][4], bs[2][4];
            #pragma unroll
            for (int g = 0; g < 2; g++) {
                uint32_t nb = (uint32_t)((n_base + g * 16) * 80) + j * 32 + boff;
                ldm4(bc[g], base + O1_CB4 + nb);
                ldm4(bs[g], base + O1_SB4 + nb);
            }
            #pragma unroll
            for (int ni = 0; ni < 4; ni++) {
                mma16(dP[0][ni], aE,  &bc[ni >> 1][(ni & 1) * 2]);
                mma16(dQ[0][ni], aO,  &bs[ni >> 1][(ni & 1) * 2]);
                mma16(dP[1][ni], aE2, &bc[ni >> 1][(ni & 1) * 2]);
                mma16(dQ[1][ni], aO2, &bs[ni >> 1][(ni & 1) * 2]);
            }
        }
    };

    load(0, 0); CP_COMMIT;
    load(1, 1); CP_COMMIT;
    load(2, 2); CP_COMMIT;
    #pragma unroll 1
    for (int ch = 0; ch < 16; ch++) {
        PIPE_WAIT(ch);
        __syncthreads();
        compute(ch & 3);
        if (ch + 3 < 16) { load(ch + 3, (ch + 3) & 3); CP_COMMIT; }
    }
    __syncthreads();

    // epilogue: Pe += (-1)^k x512e; transpose 64x128 tiles; write PeT/QoT
    __half* trs = (__half*)dsu;
    #pragma unroll
    for (int mi = 0; mi < 2; mi++) {
        int rl = m_base + mi * 16 + gr;
        float xa = g_x512e[m0 + rl];
        float xb = g_x512e[m0 + rl + 8];
        #pragma unroll
        for (int ni = 0; ni < 4; ni++) {
            int cl = n_base + ni * 8 + 2 * tg;
            trs[cl * TSTR1 + rl]           = __float2half_rn(dP[mi][ni][0] + xa);
            trs[(cl + 1) * TSTR1 + rl]     = __float2half_rn(dP[mi][ni][1] - xa);
            trs[cl * TSTR1 + rl + 8]       = __float2half_rn(dP[mi][ni][2] + xb);
            trs[(cl + 1) * TSTR1 + rl + 8] = __float2half_rn(dP[mi][ni][3] - xb);
        }
    }
    __syncthreads();
    #pragma unroll
    for (int pass = 0; pass < 4; pass++) {
        int idx = tid + pass * 256;
        int c = idx >> 3, s = idx & 7;
        uint4 v = *(uint4*)((uint32_t*)trs + c * (TSTR1 / 2) + s * 4);
        *(uint4*)(g_PeT + (size_t)(n0 + c) * MFE + m0 + s * 8) = v;
    }
    __syncthreads();
    #pragma unroll
    for (int mi = 0; mi < 2; mi++) {
        int rl = m_base + mi * 16 + gr;
        #pragma unroll
        for (int ni = 0; ni < 4; ni++) {
            int cl = n_base + ni * 8 + 2 * tg;
            trs[cl * TSTR1 + rl]           = __float2half_rn(dQ[mi][ni][0]);
            trs[(cl + 1) * TSTR1 + rl]     = __float2half_rn(dQ[mi][ni][1]);
            trs[cl * TSTR1 + rl + 8]       = __float2half_rn(dQ[mi][ni][2]);
            trs[(cl + 1) * TSTR1 + rl + 8] = __float2half_rn(dQ[mi][ni][3]);
        }
    }
    __syncthreads();
    #pragma unroll
    for (int pass = 0; pass < 4; pass++) {
        int idx = tid + pass * 256;
        int c = idx >> 3, s = idx & 7;
        uint4 v = *(uint4*)((uint32_t*)trs + c * (TSTR1 / 2) + s * 4);
        *(uint4*)(g_QoT + (size_t)(n0 + c) * MFE + m0 + s * 8) = v;
    }
}

// ---------------- tail: row 512 GEMV + Nyquist column (MUFU) ----------------
__global__ __launch_bounds__(256)
void tail512(float* __restrict__ out) {
    const int b = blockIdx.y;
    const int wid = threadIdx.x >> 5, lane = threadIdx.x & 31;
    if (blockIdx.x < 64) {
        const int k = blockIdx.x * 8 + wid;
        const __half* row = g_PeT + (size_t)k * MFE + b * 512;
        float acc = 0.f;
        #pragma unroll 4
        for (int q = 0; q < 16; q++) acc += __half2float(row[lane + q * 32]);
        float sgn = (lane & 1) ? -1.f : 1.f;
        acc *= sgn;
        #pragma unroll
        for (int o = 16; o; o >>= 1) acc += __shfl_xor_sync(0xFFFFFFFFu, acc, o);
        if (lane == 0) {
            float v = acc + __half2float(g_PeT[(size_t)k * MFE + MF + b]);
            float* orow = out + ((size_t)b * SEQ + 512) * HID;
            orow[k] = v;
            if (k != 0) orow[HID - k] = v;
        }
    } else {
        __shared__ float pv[1024];
        for (int q = threadIdx.x; q < 1024; q += 256)
            pv[q] = g_p512[b * 1024 + q];
        __syncthreads();
        const int n = (blockIdx.x - 64) * 8 + wid;
        if (n <= 512) {
            float acc = 0.f;
            #pragma unroll 8
            for (int q = 0; q < 32; q++) {
                int i = q * 32 + lane;
                int m = (n * i) & 1023;
                acc += cospif((float)m * (1.0f / 512.0f)) * pv[i];
            }
            #pragma unroll
            for (int o = 16; o; o >>= 1) acc += __shfl_xor_sync(0xFFFFFFFFu, acc, o);
            if (lane == 0) {
                out[((size_t)b * SEQ + n) * HID + 512] = acc;
                if (n >= 1 && n <= 511)
                    out[((size_t)b * SEQ + 1024 - n) * HID + 512] = acc;
            }
        }
    }
}

// ---------------- stage 2: A = C@Pe + corr, B = S@Qo; staged coalesced scatter ----------------
// CTA 128(n) x 64(k), 8 warps 4Mx2N, warp 32x32, BK=32, 16 chunks, 4-stage pipeline.
#define S2_BUF  7680
#define O2_CB4  0
#define O2_SB4  (2560 * 4)
#define O2_PB4  (5120 * 4)
#define O2_QB4  (6400 * 4)
#define SMEM2_BYTES (4 * S2_BUF * 4)
#define OST 68   // staging tile stride (floats)

__global__ __launch_bounds__(256)
void stage2(float* __restrict__ out) {
    extern __shared__ uint32_t dsu[];

    const int tid = threadIdx.x;
    const int lane = tid & 31, wid = tid >> 5;
    const int gr = lane >> 2, tg = lane & 3;
    const int m_base = (wid & 3) * 32, n_base = (wid >> 2) * 32;
    const int k0   = blockIdx.x * 64;
    const int row0 = blockIdx.y * 128;
    const int b    = blockIdx.z;

    const uint32_t aoff = (uint32_t)((m_base + (lane & 7) + ((lane >> 3) & 1) * 8) * 80
                                     + ((lane >> 4) & 1) * 16);
    const uint32_t boff = (uint32_t)(((lane & 7) + ((lane >> 4) & 1) * 8) * 80
                                     + ((lane >> 3) & 1) * 16);

    float dA[2][4][4] = {};
    float dB[2][4][4] = {};

    auto load = [&](int ch, int buf) {
        const int i0 = ch * 32;
        uint32_t* base = dsu + buf * S2_BUF;
        #pragma unroll
        for (int i = 0; i < 2; i++) {
            int t2 = tid + i * 256;
            int r = t2 >> 2, c = t2 & 3;
            uint32_t off = r * 20 + c * 4;
            size_t gsrc = (size_t)(row0 + r) * NKC + i0 + c * 8;
            cpa(smem_u32(base + off),        g_cosh + gsrc);
            cpa(smem_u32(base + 2560 + off), g_sinh + gsrc);
        }
        {
            int r = tid >> 2, c = tid & 3;
            uint32_t off = r * 20 + c * 4;
            size_t gsrc = (size_t)(k0 + r) * MFE + b * 512 + i0 + c * 8;
            cpa(smem_u32(base + 5120 + off), g_PeT + gsrc);
            cpa(smem_u32(base + 6400 + off), g_QoT + gsrc);
        }
    };

    auto compute = [&](int buf) {
        const uint32_t base = smem_u32(dsu + buf * S2_BUF);
        #pragma unroll
        for (int j = 0; j < 2; j++) {
            uint32_t aC[2][4], aS[2][4];
            #pragma unroll
            for (int mi = 0; mi < 2; mi++) {
                ldm4(aC[mi], base + O2_CB4 + aoff + mi * 1280 + j * 32);
                ldm4(aS[mi], base + O2_SB4 + aoff + mi * 1280 + j * 32);
            }
            uint32_t bP[2][4], bQ[2][4];
            #pragma unroll
            for (int g = 0; g < 2; g++) {
                uint32_t nb = (uint32_t)((n_base + g * 16) * 80) + j * 32 + boff;
                ldm4(bP[g], base + O2_PB4 + nb);
                ldm4(bQ[g], base + O2_QB4 + nb);
            }
            #pragma unroll
            for (int mi = 0; mi < 2; mi++)
                #pragma unroll
                for (int ni = 0; ni < 4; ni++) {
                    mma16(dA[mi][ni], aC[mi], &bP[ni >> 1][(ni & 1) * 2]);
                    mma16(dB[mi][ni], aS[mi], &bQ[ni >> 1][(ni & 1) * 2]);
                }
        }
    };

    load(0, 0); CP_COMMIT;
    load(1, 1); CP_COMMIT;
    load(2, 2); CP_COMMIT;
    #pragma unroll 1
    for (int ch = 0; ch < 16; ch++) {
        PIPE_WAIT(ch);
        __syncthreads();
        compute(ch & 3);
        if (ch + 3 < 16) { load(ch + 3, (ch + 3) & 3); CP_COMMIT; }
    }

    // ---- corr values into registers ----
    __syncthreads();
    float* scp = (float*)dsu;
    if (tid < 64)
        scp[tid] = __half2float(g_PeT[(size_t)(k0 + tid) * MFE + MF + b]);
    __syncthreads();
    const float sgn = (gr & 1) ? -1.f : 1.f;
    float corr[4][2];
    #pragma unroll
    for (int ni = 0; ni < 4; ni++) {
        int lc = n_base + ni * 8 + 2 * tg;
        corr[ni][0] = sgn * scp[lc];
        corr[ni][1] = sgn * scp[lc + 1];
    }
    __syncthreads();

    float* st = (float*)dsu;           // staging tile [128][OST]
    float* outb = out + (size_t)b * SEQ * HID;

    // ======== pass 1: d = A - B → direct quadrant + double-mirror quadrant ========
    #pragma unroll
    for (int mi = 0; mi < 2; mi++) {
        #pragma unroll
        for (int ni = 0; ni < 4; ni++) {
            int c = n_base + ni * 8 + 2 * tg;
            #pragma unroll
            for (int h = 0; h < 2; h++) {
                int r = m_base + mi * 16 + gr + h * 8;
                st[r * OST + c]     = (dA[mi][ni][h * 2]     + corr[ni][0]) - dB[mi][ni][h * 2];
                st[r * OST + c + 1] = (dA[mi][ni][h * 2 + 1] + corr[ni][1]) - dB[mi][ni][h * 2 + 1];
            }
        }
    }
    __syncthreads();
    for (int t = tid; t < 2048; t += 256) {
        int r = t >> 4, c4 = (t & 15) * 4;
        float4 v = *(float4*)&st[r * OST + c4];
        *(float4*)&outb[(size_t)(row0 + r) * HID + k0 + c4] = v;
    }
    for (int t = tid; t < 2048; t += 256) {
        int r = t >> 4, seg = t & 15;
        int n = row0 + r;
        if (n == 0) continue;
        float* mrow = outb + (size_t)(1024 - n) * HID;
        if (seg < 15) {
            int oc = 964 - k0 + seg * 4;
            float4 v;
            v.x = st[r * OST + (60 - seg * 4)];
            v.y = st[r * OST + (60 - seg * 4 - 1)];
            v.z = st[r * OST + (60 - seg * 4 - 2)];
            v.w = st[r * OST + (60 - seg * 4 - 3)];
            *(float4*)&mrow[oc] = v;
        } else {
            mrow[961 - k0] = st[r * OST + 63];
            mrow[962 - k0] = st[r * OST + 62];
            mrow[963 - k0] = st[r * OST + 61];
            if (k0 > 0) mrow[1024 - k0] = st[r * OST + 0];
        }
    }
    __syncthreads();

    // ======== pass 2: s = A + B → row-mirror quadrant + col-mirror quadrant ========
    #pragma unroll
    for (int mi = 0; mi < 2; mi++) {
        #pragma unroll
        for (int ni = 0; ni < 4; ni++) {
            int c = n_base + ni * 8 + 2 * tg;
            #pragma unroll
            for (int h = 0; h < 2; h++) {
                int r = m_base + mi * 16 + gr + h * 8;
                st[r * OST + c]     = (dA[mi][ni][h * 2]     + corr[ni][0]) + dB[mi][ni][h * 2];
                st[r * OST + c + 1] = (dA[mi][ni][h * 2 + 1] + corr[ni][1]) + dB[mi][ni][h * 2 + 1];
            }
        }
    }
    __syncthreads();
    for (int t = tid; t < 2048; t += 256) {
        int r = t >> 4, c4 = (t & 15) * 4;
        int n = row0 + r;
        if (n == 0) continue;
        float4 v = *(float4*)&st[r * OST + c4];
        *(float4*)&outb[(size_t)(1024 - n) * HID + k0 + c4] = v;
    }
    for (int t = tid; t < 2048; t += 256) {
        int r = t >> 4, seg = t & 15;
        int n = row0 + r;
        float* orow = outb + (size_t)n * HID;
        if (seg < 15) {
            int oc = 964 - k0 + seg * 4;
            float4 v;
            v.x = st[r * OST + (60 - seg * 4)];
            v.y = st[r * OST + (60 - seg * 4 - 1)];
            v.z = st[r * OST + (60 - seg * 4 - 2)];
            v.w = st[r * OST + (60 - seg * 4 - 3)];
            *(float4*)&orow[oc] = v;
        } else {
            orow[961 - k0] = st[r * OST + 63];
            orow[962 - k0] = st[r * OST + 62];
            orow[963 - k0] = st[r * OST + 61];
            if (k0 > 0) orow[1024 - k0] = st[r * OST + 0];
        }
    }
}

// ---------------- launcher ----------------
extern "C" void kernel_launch(void* const* d_in, const int* in_sizes, int n_in,
                              void* d_out, int out_size) {
    const float* X = (const float*)d_in[0];
    float* out = (float*)d_out;

    cudaFuncSetAttribute(stage1, cudaFuncAttributeMaxDynamicSharedMemorySize, SMEM1_BYTES);
    cudaFuncSetAttribute(stage2, cudaFuncAttributeMaxDynamicSharedMemorySize, SMEM2_BYTES);

    foldX2<<<dim3(512 + 256, 4), 256>>>(X);
    stage1<<<dim3(4, 33), 256, SMEM1_BYTES>>>();
    tail512<<<dim3(129, 4), 256>>>(out);
    stage2<<<dim3(8, 4, 4), 256, SMEM2_BYTES>>>(out);
}

// round 17
// speedup vs baseline: 1.1689x; 1.0447x over previous
#include <cuda_runtime.h>
#include <cuda_fp16.h>
#include <cstdint>

#define SEQ   1024
#define HID   1024
#define BATCH 4
#define NROWS (BATCH * 1024)
#define NKC   512
#define MF    (BATCH * 512)        // 2048 folded rows
#define MFE   (MF + 64)            // extended with row-512 tile (4 used, 60 zero)

// ---------------- static device scratch ----------------
__device__ __half g_cosh[NKC * NKC];      // cos quadrant [n<512][k<512] (stage1 B operand)
__device__ __half g_sinh[NKC * NKC];
__device__ __half g_cosh2[256 * NKC];     // stage2 A: rows n<256, cols parity-permuted i
__device__ __half g_sinh2[256 * NKC];
__device__ __half g_XeE[MFE * NKC];       // double-even fold of X (fp16)
__device__ __half g_XoO[MFE * NKC];
__device__ float  g_x512e[MFE];
__device__ __half g_PeT[NKC * MFE];       // Pe^T, cols parity-permuted within batch; ext cols identity
__device__ __half g_QoT[NKC * MFE];
__device__ float  g_p512[NROWS];

// ---------------- helpers ----------------
__device__ __forceinline__ uint32_t smem_u32(const void* p) {
    return (uint32_t)__cvta_generic_to_shared(p);
}
__device__ __forceinline__ void cpa(uint32_t s, const void* g) {
    asm volatile("cp.async.cg.shared.global [%0], [%1], 16;" :: "r"(s), "l"(g));
}
#define CP_COMMIT asm volatile("cp.async.commit_group;" ::: "memory")
#define CP_WAIT2  asm volatile("cp.async.wait_group 2;" ::: "memory")
#define CP_WAIT1  asm volatile("cp.async.wait_group 1;" ::: "memory")
#define CP_WAIT0  asm volatile("cp.async.wait_group 0;" ::: "memory")

__device__ __forceinline__ void mma16(float* d, const uint32_t* a, const uint32_t* b) {
    asm volatile(
        "mma.sync.aligned.m16n8k16.row.col.f32.f16.f16.f32 "
        "{%0,%1,%2,%3}, {%4,%5,%6,%7}, {%8,%9}, {%0,%1,%2,%3};"
        : "+f"(d[0]), "+f"(d[1]), "+f"(d[2]), "+f"(d[3])
        : "r"(a[0]), "r"(a[1]), "r"(a[2]), "r"(a[3]), "r"(b[0]), "r"(b[1]));
}
__device__ __forceinline__ void ldm4(uint32_t* r, uint32_t saddr) {
    asm volatile("ldmatrix.sync.aligned.m8n8.x4.shared.b16 {%0,%1,%2,%3}, [%4];"
        : "=r"(r[0]), "=r"(r[1]), "=r"(r[2]), "=r"(r[3]) : "r"(saddr));
}

#define PIPE_WAIT(ch) do { \
    if ((ch) <= 13) { CP_WAIT2; } \
    else if ((ch) == 14) { CP_WAIT1; } \
    else { CP_WAIT0; } \
} while (0)

// ---------------- fused: fold X + Nyquist row-sums + table fills ----------------
__global__ __launch_bounds__(256)
void foldX2(const float* __restrict__ X) {
    if (blockIdx.x >= 512) {
        int fb = (blockIdx.x - 512) + 384 * blockIdx.y;   // 0..1535
        if (fb < 1024) {
            int idx = fb * 256 + threadIdx.x;             // 512x512 quadrant
            int j = idx >> 9, k = idx & 511;
            int m = (j * k) & 1023;
            float s, c;
            sincospif((float)m * (1.0f / 512.0f), &s, &c);
            g_cosh[idx] = __float2half_rn(c);
            g_sinh[idx] = __float2half_rn(s);
        } else {
            int idx = (fb - 1024) * 256 + threadIdx.x;    // 256x512 parity tables
            int n = idx >> 9, q = idx & 511;
            int i = 2 * (q & 255) + (q >> 8);             // permuted col -> original i
            int m = (n * i) & 1023;
            float s, c;
            sincospif((float)m * (1.0f / 512.0f), &s, &c);
            g_cosh2[idx] = __float2half_rn(c);
            g_sinh2[idx] = __float2half_rn(s);
        }
        return;
    }

    __shared__ float se[512], so[512];
    __shared__ float s_red[8];
    __shared__ float sx5[2];
    const int tid = threadIdx.x;
    const int rloc = tid >> 7;
    const int l128 = tid & 127;
    const int kg = l128 * 4;
    const int i = blockIdx.x;
    const int b = blockIdx.y;
    const int r = rloc ? (i == 0 ? b * 1024 + 512 : b * 1024 + 1024 - i)
                       : (b * 1024 + i);
    const float* Xrow = X + (size_t)r * HID;

    float4 fx = *(const float4*)(Xrow + kg);
    float fv[4] = { fx.x, fx.y, fx.z, fx.w };
    float e[4], o[4];
    float part = 0.f;
    #pragma unroll
    for (int j = 0; j < 4; j++) {
        int k = kg + j;
        if (k == 0) {
            e[0] = fv[0]; o[0] = 0.f;
            part += fv[0];
        } else {
            float m = Xrow[1024 - k];
            float sum = fv[j] + m, dif = fv[j] - m;
            e[j] = sum;
            o[j] = dif;
            part += (k & 1) ? -sum : sum;
        }
    }
    if (kg == 0) {
        float x5 = Xrow[512];
        sx5[rloc] = x5;
        part += x5;
    }
    if (rloc == 1 && i != 0) {
        *(float4*)(se + kg) = make_float4(e[0], e[1], e[2], e[3]);
        *(float4*)(so + kg) = make_float4(o[0], o[1], o[2], o[3]);
    }
    #pragma unroll
    for (int off = 16; off; off >>= 1) part += __shfl_xor_sync(0xFFFFFFFFu, part, off);
    if ((tid & 31) == 0) s_red[tid >> 5] = part;
    __syncthreads();
    if ((tid & 127) == 0) {
        int w0 = rloc * 4;
        g_p512[r] = s_red[w0] + s_red[w0 + 1] + s_red[w0 + 2] + s_red[w0 + 3];
    }
    if (rloc == 0) {
        float eE[4], oO[4];
        if (i == 0) {
            #pragma unroll
            for (int j = 0; j < 4; j++) { eE[j] = e[j]; oO[j] = 0.f; }
        } else {
            #pragma unroll
            for (int j = 0; j < 4; j++) {
                eE[j] = e[j] + se[kg + j];
                oO[j] = o[j] - so[kg + j];
            }
        }
        size_t dst = ((size_t)b * 512 + i) * NKC + kg;
        *(half2*)(g_XeE + dst)     = __floats2half2_rn(eE[0], eE[1]);
        *(half2*)(g_XeE + dst + 2) = __floats2half2_rn(eE[2], eE[3]);
        *(half2*)(g_XoO + dst)     = __floats2half2_rn(oO[0], oO[1]);
        *(half2*)(g_XoO + dst + 2) = __floats2half2_rn(oO[2], oO[3]);
        if (kg == 0)
            g_x512e[b * 512 + i] = (i == 0) ? sx5[0] : sx5[0] + sx5[1];
    } else if (i == 0) {
        size_t dst = ((size_t)MF + b) * NKC + kg;
        *(half2*)(g_XeE + dst)     = __floats2half2_rn(e[0], e[1]);
        *(half2*)(g_XeE + dst + 2) = __floats2half2_rn(e[2], e[3]);
        if (kg == 0) g_x512e[MF + b] = sx5[1];   // X[b,512,512]
    }
}

// ---------------- stage 1: PeT/QoT = (XeE@C)^T, (XoO@S)^T; parity-permuted cols ----------------
#define S1_BUF  7680
#define O1_XE4  0
#define O1_XO4  (1280 * 4)
#define O1_CB4  (2560 * 4)
#define O1_SB4  (5120 * 4)
#define SMEM1_BYTES (4 * S1_BUF * 4)
#define TSTR1   72

__global__ __launch_bounds__(256)
void stage1() {
    extern __shared__ uint32_t dsu[];

    const int tid = threadIdx.x;
    const int lane = tid & 31, wid = tid >> 5;
    const int gr = lane >> 2, tg = lane & 3;
    const int m_base = (wid & 1) * 32, n_base = (wid >> 1) * 32;
    const int m0 = blockIdx.y * 64;
    const int n0 = blockIdx.x * 128;

    const uint32_t aoff = (uint32_t)((m_base + (lane & 7) + ((lane >> 3) & 1) * 8) * 80
                                     + ((lane >> 4) & 1) * 16);
    const uint32_t boff = (uint32_t)(((lane & 7) + ((lane >> 4) & 1) * 8) * 80
                                     + ((lane >> 3) & 1) * 16);

    float dP[2][4][4] = {};
    float dQ[2][4][4] = {};

    auto load = [&](int ch, int buf) {
        const int k0h = ch * 32;
        uint32_t* base = dsu + buf * S1_BUF;
        {
            int r = tid >> 2, c = tid & 3;
            uint32_t off = r * 20 + c * 4;
            size_t ga = (size_t)(m0 + r) * NKC + k0h + c * 8;
            cpa(smem_u32(base + off),        g_XeE + ga);
            cpa(smem_u32(base + 1280 + off), g_XoO + ga);
        }
        #pragma unroll
        for (int i = 0; i < 2; i++) {
            int t = tid + i * 256;
            int r = t >> 2, c = t & 3;
            uint32_t off = r * 20 + c * 4;
            size_t gb = (size_t)(n0 + r) * NKC + k0h + c * 8;
            cpa(smem_u32(base + 2560 + off), g_cosh + gb);
            cpa(smem_u32(base + 5120 + off), g_sinh + gb);
        }
    };

    auto compute = [&](int buf) {
        const uint32_t base = smem_u32(dsu + buf * S1_BUF);
        #pragma unroll
        for (int j = 0; j < 2; j++) {
            uint32_t aE[4], aO[4], aE2[4], aO2[4];
            ldm4(aE,  base + O1_XE4 + aoff + j * 32);
            ldm4(aO,  base + O1_XO4 + aoff + j * 32);
            ldm4(aE2, base + O1_XE4 + aoff + 1280 + j * 32);
            ldm4(aO2, base + O1_XO4 + aoff + 1280 + j * 32);
            uint32_t bc[2][4], bs[2][4];
            #pragma unroll
            for (int g = 0; g < 2; g++) {
                uint32_t nb = (uint32_t)((n_base + g * 16) * 80) + j * 32 + boff;
                ldm4(bc[g], base + O1_CB4 + nb);
                ldm4(bs[g], base + O1_SB4 + nb);
            }
            #pragma unroll
            for (int ni = 0; ni < 4; ni++) {
                mma16(dP[0][ni], aE,  &bc[ni >> 1][(ni & 1) * 2]);
                mma16(dQ[0][ni], aO,  &bs[ni >> 1][(ni & 1) * 2]);
                mma16(dP[1][ni], aE2, &bc[ni >> 1][(ni & 1) * 2]);
                mma16(dQ[1][ni], aO2, &bs[ni >> 1][(ni & 1) * 2]);
            }
        }
    };

    load(0, 0); CP_COMMIT;
    load(1, 1); CP_COMMIT;
    load(2, 2); CP_COMMIT;
    #pragma unroll 1
    for (int ch = 0; ch < 16; ch++) {
        PIPE_WAIT(ch);
        __syncthreads();
        compute(ch & 3);
        if (ch + 3 < 16) { load(ch + 3, (ch + 3) & 3); CP_COMMIT; }
    }
    __syncthreads();

    // epilogue: Pe += (-1)^k x512e; transpose; write with parity-permuted cols
    __half* trs = (__half*)dsu;

    auto write_permuted = [&](__half* dstT) {
        if (m0 < MF) {
            int bb = m0 >> 9, mb = m0 & 511;
            #pragma unroll
            for (int pass = 0; pass < 2; pass++) {
                int idx = tid + pass * 256;
                int c = idx >> 2, sg = idx & 3;       // row, 16-half segment
                uint32_t* rowp = (uint32_t*)trs + c * (TSTR1 / 2) + sg * 8;
                uint4 lo = *(uint4*)rowp;
                uint4 hi = *(uint4*)(rowp + 4);
                uint4 ev, od;
                ev.x = __byte_perm(lo.x, lo.y, 0x5410);
                ev.y = __byte_perm(lo.z, lo.w, 0x5410);
                ev.z = __byte_perm(hi.x, hi.y, 0x5410);
                ev.w = __byte_perm(hi.z, hi.w, 0x5410);
                od.x = __byte_perm(lo.x, lo.y, 0x7632);
                od.y = __byte_perm(lo.z, lo.w, 0x7632);
                od.z = __byte_perm(hi.x, hi.y, 0x7632);
                od.w = __byte_perm(hi.z, hi.w, 0x7632);
                __half* dstE = dstT + (size_t)(n0 + c) * MFE + bb * 512 + (mb >> 1) + sg * 8;
                *(uint4*)dstE = ev;
                *(uint4*)(dstE + 256) = od;
            }
        } else {
            #pragma unroll
            for (int pass = 0; pass < 4; pass++) {
                int idx = tid + pass * 256;
                int c = idx >> 3, s = idx & 7;
                uint4 v = *(uint4*)((uint32_t*)trs + c * (TSTR1 / 2) + s * 4);
                *(uint4*)(dstT + (size_t)(n0 + c) * MFE + m0 + s * 8) = v;
            }
        }
    };

    #pragma unroll
    for (int mi = 0; mi < 2; mi++) {
        int rl = m_base + mi * 16 + gr;
        float xa = g_x512e[m0 + rl];
        float xb = g_x512e[m0 + rl + 8];
        #pragma unroll
        for (int ni = 0; ni < 4; ni++) {
            int cl = n_base + ni * 8 + 2 * tg;
            trs[cl * TSTR1 + rl]           = __float2half_rn(dP[mi][ni][0] + xa);
            trs[(cl + 1) * TSTR1 + rl]     = __float2half_rn(dP[mi][ni][1] - xa);
            trs[cl * TSTR1 + rl + 8]       = __float2half_rn(dP[mi][ni][2] + xb);
            trs[(cl + 1) * TSTR1 + rl + 8] = __float2half_rn(dP[mi][ni][3] - xb);
        }
    }
    __syncthreads();
    write_permuted(g_PeT);
    __syncthreads();
    #pragma unroll
    for (int mi = 0; mi < 2; mi++) {
        int rl = m_base + mi * 16 + gr;
        #pragma unroll
        for (int ni = 0; ni < 4; ni++) {
            int cl = n_base + ni * 8 + 2 * tg;
            trs[cl * TSTR1 + rl]           = __float2half_rn(dQ[mi][ni][0]);
            trs[(cl + 1) * TSTR1 + rl]     = __float2half_rn(dQ[mi][ni][1]);
            trs[cl * TSTR1 + rl + 8]       = __float2half_rn(dQ[mi][ni][2]);
            trs[(cl + 1) * TSTR1 + rl + 8] = __float2half_rn(dQ[mi][ni][3]);
        }
    }
    __syncthreads();
    write_permuted(g_QoT);
}

// ---------------- tail: rows 256/768 GEMV + Nyquist column ----------------
__global__ __launch_bounds__(256)
void tail512(float* __restrict__ out) {
    const int b = blockIdx.y;
    const int wid = threadIdx.x >> 5, lane = threadIdx.x & 31;
    if (blockIdx.x < 64) {
        // A = sum_{q<256} (-1)^q PeT_perm[k][b512+q] + P512[k]
        // B = sum_{q<256} (-1)^q QoT_perm[k][b512+256+q]
        const int k = blockIdx.x * 8 + wid;
        const __half* pe = g_PeT + (size_t)k * MFE + b * 512;
        const __half* qo = g_QoT + (size_t)k * MFE + b * 512 + 256;
        float accA = 0.f, accB = 0.f;
        #pragma unroll 4
        for (int q = 0; q < 8; q++) {
            accA += __half2float(pe[lane + q * 32]);
            accB += __half2float(qo[lane + q * 32]);
        }
        float sgn = (lane & 1) ? -1.f : 1.f;
        accA *= sgn; accB *= sgn;
        #pragma unroll
        for (int o = 16; o; o >>= 1) {
            accA += __shfl_xor_sync(0xFFFFFFFFu, accA, o);
            accB += __shfl_xor_sync(0xFFFFFFFFu, accB, o);
        }
        if (lane == 0) {
            float A = accA + __half2float(g_PeT[(size_t)k * MFE + MF + b]);
            float B = accB;
            float* r256 = out + ((size_t)b * SEQ + 256) * HID;
            float* r768 = out + ((size_t)b * SEQ + 768) * HID;
            r256[k] = A - B;
            r768[k] = A + B;
            if (k != 0) {
                r256[HID - k] = A + B;
                r768[HID - k] = A - B;
            }
        }
    } else {
        __shared__ float pv[1024];
        for (int q = threadIdx.x; q < 1024; q += 256)
            pv[q] = g_p512[b * 1024 + q];
        __syncthreads();
        const int n = (blockIdx.x - 64) * 8 + wid;
        if (n <= 512) {
            float acc = 0.f;
            #pragma unroll 8
            for (int q = 0; q < 32; q++) {
                int i = q * 32 + lane;
                int m = (n * i) & 1023;
                acc += cospif((float)m * (1.0f / 512.0f)) * pv[i];
            }
            #pragma unroll
            for (int o = 16; o; o >>= 1) acc += __shfl_xor_sync(0xFFFFFFFFu, acc, o);
            if (lane == 0) {
                out[((size_t)b * SEQ + n) * HID + 512] = acc;
                if (n >= 1 && n <= 511)
                    out[((size_t)b * SEQ + 1024 - n) * HID + 512] = acc;
            }
        }
    }
}

// ---------------- stage 2 (parity-folded): E/O over i-parity; 8 output regions ----------------
// CTA 128(n, n<256) x 32(k). 8 warps (4M x 2N), warp 32x16. 16 chunks: 0-7 even block -> E,
// 8-15 odd block -> O. Rows {n, 1024-n, 512-n, 512+n} x {direct, mirrored} cols.
#define S2_BUF  6400
#define O2_CB4  0
#define O2_SB4  (2560 * 4)
#define O2_PB4  (5120 * 4)
#define O2_QB4  (5760 * 4)
#define SMEM2_BYTES (4 * S2_BUF * 4)
#define OST2 36

__global__ __launch_bounds__(256)
void stage2(float* __restrict__ out) {
    extern __shared__ uint32_t dsu[];

    const int tid = threadIdx.x;
    const int lane = tid & 31, wid = tid >> 5;
    const int gr = lane >> 2, tg = lane & 3;
    const int m_base = (wid >> 1) * 32, n_base = (wid & 1) * 16;
    const int k0   = blockIdx.x * 32;
    const int row0 = blockIdx.y * 128;   // 0 or 128
    const int b    = blockIdx.z;

    const uint32_t aoff = (uint32_t)((m_base + (lane & 7) + ((lane >> 3) & 1) * 8) * 80
                                     + ((lane >> 4) & 1) * 16);
    const uint32_t boff = (uint32_t)(((lane & 7) + ((lane >> 4) & 1) * 8) * 80
                                     + ((lane >> 3) & 1) * 16);

    float EA[2][2][4] = {}, OA[2][2][4] = {};
    float EB[2][2][4] = {}, OB[2][2][4] = {};

    auto load = [&](int ch, int buf) {
        const int i0 = ch * 32;
        uint32_t* base = dsu + buf * S2_BUF;
        #pragma unroll
        for (int i = 0; i < 2; i++) {
            int t2 = tid + i * 256;
            int r = t2 >> 2, c = t2 & 3;
            uint32_t off = r * 20 + c * 4;
            size_t gsrc = (size_t)(row0 + r) * NKC + i0 + c * 8;
            cpa(smem_u32(base + off),        g_cosh2 + gsrc);
            cpa(smem_u32(base + 2560 + off), g_sinh2 + gsrc);
        }
        {
            int r = (tid & 127) >> 2, c = tid & 3;
            uint32_t off = r * 20 + c * 4;
            size_t gsrc = (size_t)(k0 + r) * MFE + b * 512 + i0 + c * 8;
            if (tid < 128) cpa(smem_u32(base + 5120 + off), g_PeT + gsrc);
            else           cpa(smem_u32(base + 5760 + off), g_QoT + gsrc);
        }
    };

    auto compute = [&](int buf, float (*dA)[2][4], float (*dB)[2][4]) {
        const uint32_t base = smem_u32(dsu + buf * S2_BUF);
        #pragma unroll
        for (int j = 0; j < 2; j++) {
            uint32_t aC[2][4], aS[2][4];
            #pragma unroll
            for (int mi = 0; mi < 2; mi++) {
                ldm4(aC[mi], base + O2_CB4 + aoff + mi * 1280 + j * 32);
                ldm4(aS[mi], base + O2_SB4 + aoff + mi * 1280 + j * 32);
            }
            uint32_t bP[4], bQ[4];
            uint32_t nb = (uint32_t)(n_base * 80) + j * 32 + boff;
            ldm4(bP, base + O2_PB4 + nb);
            ldm4(bQ, base + O2_QB4 + nb);
            #pragma unroll
            for (int mi = 0; mi < 2; mi++)
                #pragma unroll
                for (int ni = 0; ni < 2; ni++) {
                    mma16(dA[mi][ni], aC[mi], &bP[ni * 2]);
                    mma16(dB[mi][ni], aS[mi], &bQ[ni * 2]);
                }
        }
    };

    load(0, 0); CP_COMMIT;
    load(1, 1); CP_COMMIT;
    load(2, 2); CP_COMMIT;
    #pragma unroll 1
    for (int ch = 0; ch < 16; ch++) {
        PIPE_WAIT(ch);
        __syncthreads();
        if (ch < 8) compute(ch & 3, EA, EB);
        else        compute(ch & 3, OA, OB);
        if (ch + 3 < 16) { load(ch + 3, (ch + 3) & 3); CP_COMMIT; }
    }

    // corr (attaches to E_A; same sign for rows n and 512-n)
    __syncthreads();
    float* scp = (float*)dsu;
    if (tid < 32)
        scp[tid] = __half2float(g_PeT[(size_t)(k0 + tid) * MFE + MF + b]);
    __syncthreads();
    const float sgn = (gr & 1) ? -1.f : 1.f;
    float corr[2][2];
    #pragma unroll
    for (int ni = 0; ni < 2; ni++) {
        int lc = n_base + ni * 8 + 2 * tg;
        corr[ni][0] = sgn * scp[lc];
        corr[ni][1] = sgn * scp[lc + 1];
    }
    __syncthreads();

    float* st = (float*)dsu;           // staging [128][OST2]
    float* outb = out + (size_t)b * SEQ * HID;

    auto stage_combo = [&](int which) {
        #pragma unroll
        for (int mi = 0; mi < 2; mi++) {
            #pragma unroll
            for (int ni = 0; ni < 2; ni++) {
                int c = n_base + ni * 8 + 2 * tg;
                #pragma unroll
                for (int h = 0; h < 2; h++) {
                    int r = m_base + mi * 16 + gr + h * 8;
                    #pragma unroll
                    for (int u = 0; u < 2; u++) {
                        float ea = EA[mi][ni][h * 2 + u], oa = OA[mi][ni][h * 2 + u];
                        float eb = EB[mi][ni][h * 2 + u], ob = OB[mi][ni][h * 2 + u];
                        float ap = ea + oa + corr[ni][u];
                        float am = ea - oa + corr[ni][u];
                        float bp = eb + ob, bm = eb - ob;
                        float v = (which == 0) ? ap - bp
                                : (which == 1) ? ap + bp
                                : (which == 2) ? am + bm
                                               : am - bm;
                        st[r * OST2 + c + u] = v;
                    }
                }
            }
        }
    };
    // rowKind: 0 -> n; 1 -> 1024-n (skip n==0); 2 -> 512-n; 3 -> 512+n (skip n==0)
    auto drow = [&](int n, int kind, bool& ok) -> int {
        ok = true;
        if (kind == 0) return n;
        if (kind == 1) { ok = (n != 0); return 1024 - n; }
        if (kind == 2) return 512 - n;
        ok = (n != 0); return 512 + n;
    };
    auto store_direct = [&](int kind) {
        for (int t = tid; t < 1024; t += 256) {
            int r = t >> 3, c4 = (t & 7) * 4;
            bool ok; int dr = drow(row0 + r, kind, ok);
            if (!ok) continue;
            *(float4*)&outb[(size_t)dr * HID + k0 + c4] = *(float4*)&st[r * OST2 + c4];
        }
    };
    auto store_mirror = [&](int kind) {
        for (int t = tid; t < 1024; t += 256) {
            int r = t >> 3, seg = t & 7;
            bool ok; int dr = drow(row0 + r, kind, ok);
            if (!ok) continue;
            float* orow = outb + (size_t)dr * HID;
            const float* sr = &st[r * OST2];
            if (seg < 7) {
                int oc = 996 - k0 + seg * 4;
                float4 v;
                v.x = sr[28 - seg * 4];
                v.y = sr[27 - seg * 4];
                v.z = sr[26 - seg * 4];
                v.w = sr[25 - seg * 4];
                *(float4*)&orow[oc] = v;
            } else {
                orow[993 - k0] = sr[31];
                orow[994 - k0] = sr[30];
                orow[995 - k0] = sr[29];
                if (k0 > 0) orow[1024 - k0] = sr[0];
            }
        }
    };

    stage_combo(0); __syncthreads();
    store_direct(0); store_mirror(1);
    __syncthreads();
    stage_combo(1); __syncthreads();
    store_direct(1); store_mirror(0);
    __syncthreads();
    stage_combo(2); __syncthreads();
    store_direct(2); store_mirror(3);
    __syncthreads();
    stage_combo(3); __syncthreads();
    store_direct(3); store_mirror(2);
}

// ---------------- launcher ----------------
extern "C" void kernel_launch(void* const* d_in, const int* in_sizes, int n_in,
                              void* d_out, int out_size) {
    const float* X = (const float*)d_in[0];
    float* out = (float*)d_out;

    cudaFuncSetAttribute(stage1, cudaFuncAttributeMaxDynamicSharedMemorySize, SMEM1_BYTES);
    cudaFuncSetAttribute(stage2, cudaFuncAttributeMaxDynamicSharedMemorySize, SMEM2_BYTES);

    foldX2<<<dim3(512 + 384, 4), 256>>>(X);
    stage1<<<dim3(4, 33), 256, SMEM1_BYTES>>>();
    tail512<<<dim3(129, 4), 256>>>(out);
    stage2<<<dim3(16, 2, 4), 256, SMEM2_BYTES>>>(out);
}